// round 13
// baseline (speedup 1.0000x reference)
#include <cuda_runtime.h>
#include <cuda_fp16.h>
#include <cstdint>

#define L_SEQ 2048
#define NBATCH 4
#define HEADS 16
#define DH 64
#define EMB 1024
#define MROWS (NBATCH * L_SEQ)   // 8192
#define LOG2E 1.4426950408889634f

// fp16 scratch (no cudaMalloc allowed)
__device__ __half g_Q[NBATCH * HEADS * L_SEQ * DH];
__device__ __half g_K[NBATCH * HEADS * L_SEQ * DH];
__device__ __half g_V[NBATCH * HEADS * L_SEQ * DH];
__device__ __half g_X[MROWS * EMB];          // x in fp16
__device__ __half g_W[3][EMB * EMB];         // Wq/Wk/Wv in fp16
__device__ float  g_M[NBATCH * L_SEQ];       // mask * log2e

// ---------------------------------------------------------------------------
// helpers
// ---------------------------------------------------------------------------
__device__ __forceinline__ uint32_t h2bits(float a, float b) {
    __half2 h = __floats2half2_rn(a, b);
    return *reinterpret_cast<uint32_t*>(&h);
}

__device__ __forceinline__ uint32_t prmt(uint32_t a, uint32_t b, uint32_t c) {
    uint32_t d;
    asm("prmt.b32 %0, %1, %2, %3;" : "=r"(d) : "r"(a), "r"(b), "r"(c));
    return d;
}

__device__ __forceinline__ float ex2f(float x) {
    float r;
    asm("ex2.approx.ftz.f32 %0, %1;" : "=f"(r) : "f"(x));
    return r;
}

__device__ __forceinline__ void mma16(float* c, const uint32_t* a,
                                      uint32_t b0, uint32_t b1) {
    asm volatile(
        "mma.sync.aligned.m16n8k16.row.col.f32.f16.f16.f32 "
        "{%0,%1,%2,%3}, {%4,%5,%6,%7}, {%8,%9}, {%0,%1,%2,%3};"
        : "+f"(c[0]), "+f"(c[1]), "+f"(c[2]), "+f"(c[3])
        : "r"(a[0]), "r"(a[1]), "r"(a[2]), "r"(a[3]), "r"(b0), "r"(b1));
}

__device__ __forceinline__ void ldsm4(uint32_t& r0, uint32_t& r1,
                                      uint32_t& r2, uint32_t& r3,
                                      uint32_t addr) {
    asm volatile(
        "ldmatrix.sync.aligned.m8n8.x4.shared.b16 {%0,%1,%2,%3}, [%4];"
        : "=r"(r0), "=r"(r1), "=r"(r2), "=r"(r3) : "r"(addr));
}

__device__ __forceinline__ void cp16(uint32_t dst, const void* src) {
    asm volatile("cp.async.cg.shared.global [%0], [%1], 16;"
                 :: "r"(dst), "l"(src));
}
#define CP_COMMIT() asm volatile("cp.async.commit_group;" ::: "memory")
#define CP_WAIT0()  asm volatile("cp.async.wait_group 0;" ::: "memory")
#define CP_WAIT1()  asm volatile("cp.async.wait_group 1;" ::: "memory")

// ---------------------------------------------------------------------------
// fp32 -> fp16 conversion + mask prescale, ONE launch.
// blocks [0,XB): x; [XB, XB+3WB): weights; [XB+3WB, +MB): mask*log2e
// ---------------------------------------------------------------------------
#define XB (MROWS * EMB / 1024)     // 8192 blocks
#define WB (EMB * EMB / 1024)       // 1024 blocks
#define MB (NBATCH * L_SEQ / 1024)  // 8 blocks

__global__ __launch_bounds__(256)
void cvt_all_kernel(const float4* __restrict__ x,
                    const float4* __restrict__ Wq,
                    const float4* __restrict__ Wk,
                    const float4* __restrict__ Wv,
                    const float4* __restrict__ mask,
                    uint2* __restrict__ gx, uint2* __restrict__ gw,
                    float4* __restrict__ gm) {
    const int bid = blockIdx.x;
    if (bid >= XB + 3 * WB) {
        const int i = (bid - XB - 3 * WB) * 256 + threadIdx.x;
        const float4 v = mask[i];
        gm[i] = make_float4(v.x * LOG2E, v.y * LOG2E, v.z * LOG2E, v.w * LOG2E);
        return;
    }
    const float4* src;
    uint2* dst;
    int i;
    if (bid < XB) {
        src = x; dst = gx; i = bid * 256 + threadIdx.x;
    } else {
        const int z = (bid - XB) >> 10;
        const int b = (bid - XB) & (WB - 1);
        src = (z == 0) ? Wq : (z == 1) ? Wk : Wv;
        dst = gw + (size_t)z * (EMB * EMB / 4);
        i = b * 256 + threadIdx.x;
    }
    const float4 v = src[i];
    dst[i] = make_uint2(h2bits(v.x, v.y), h2bits(v.z, v.w));
}

// ---------------------------------------------------------------------------
// Projection GEMM, fp16 / ldmatrix / 3-stage cp.async. z picks Q/K/V.
// CTA 128m x 128n, k-tile 64, 8 warps = 2m x 4n. One barrier per k-tile.
// smem rows 144 B -> conflict-free ldmatrix. Q gets scale 0.125*log2e.
// ---------------------------------------------------------------------------
#define PRS 144                               // row stride, bytes
#define PTILE (128 * PRS)                     // 18432 B per tile
#define PROJ_SMEM (6 * PTILE)                 // 3-stage A + B = 110592 B

__global__ __launch_bounds__(256)
void proj_kernel(const __half* __restrict__ Xh, const __half* __restrict__ Wh3,
                 const float* __restrict__ bq, const float* __restrict__ bk,
                 const float* __restrict__ bv,
                 __half* __restrict__ gq, __half* __restrict__ gk,
                 __half* __restrict__ gv)
{
    extern __shared__ char smc[];
    const uint32_t sa = (uint32_t)__cvta_generic_to_shared(smc);

    const int z = blockIdx.z;
    const __half* Wh  = Wh3 + (size_t)z * EMB * EMB;
    const float* bias = (z == 0) ? bq : (z == 1) ? bk : bv;
    __half* out       = (z == 0) ? gq : (z == 1) ? gk : gv;
    const float scale = (z == 0) ? 0.125f * LOG2E : 1.0f;

    const int tid  = threadIdx.x;
    const int lane = tid & 31;
    const int warp = tid >> 5;
    const int g = lane >> 2, t = lane & 3;
    const int m0 = blockIdx.y * 128, n0 = blockIdx.x * 128;
    const int wm = warp >> 2, wn = warp & 3;

    const int a_off = ((lane & 7) | (((lane >> 3) & 1) << 3)) * PRS
                    + (lane >> 4) * 16;
    const int b_off = ((lane & 7) | ((lane >> 4) << 3)) * PRS
                    + ((lane >> 3) & 1) * 16;

    const int srow = tid >> 1;
    const int sq   = (tid & 1) * 4;
    const __half* Xp = Xh + (size_t)(m0 + srow) * EMB + sq * 8;
    const __half* Wp = Wh + (size_t)(n0 + srow) * EMB + sq * 8;
    const uint32_t Asw = srow * PRS + sq * 16;

    float acc[4][4][4];
#pragma unroll
    for (int mi = 0; mi < 4; mi++)
#pragma unroll
        for (int ni = 0; ni < 4; ni++)
#pragma unroll
            for (int e = 0; e < 4; e++) acc[mi][ni][e] = 0.0f;

    // prologue: tiles 0 and 1
#pragma unroll
    for (int s = 0; s < 2; s++) {
#pragma unroll
        for (int q = 0; q < 4; q++) {
            cp16(sa + s * PTILE + Asw + q * 16, Xp + s * 64 + q * 8);
            cp16(sa + (3 + s) * PTILE + Asw + q * 16, Wp + s * 64 + q * 8);
        }
        CP_COMMIT();
    }

    int buf = 0;
    for (int kt = 0; kt < 16; kt++) {
        if (kt == 15) { CP_WAIT0(); } else { CP_WAIT1(); }
        __syncthreads();

        if (kt < 14) {
            const int nb = (buf + 2 >= 3) ? buf - 1 : buf + 2;
#pragma unroll
            for (int q = 0; q < 4; q++) {
                cp16(sa + nb * PTILE + Asw + q * 16, Xp + (kt + 2) * 64 + q * 8);
                cp16(sa + (3 + nb) * PTILE + Asw + q * 16, Wp + (kt + 2) * 64 + q * 8);
            }
            CP_COMMIT();
        }

        const uint32_t Ab = sa + buf * PTILE;
        const uint32_t Bb = sa + (3 + buf) * PTILE;
#pragma unroll
        for (int j = 0; j < 4; j++) {
            uint32_t a[4][4];
#pragma unroll
            for (int mi = 0; mi < 4; mi++)
                ldsm4(a[mi][0], a[mi][1], a[mi][2], a[mi][3],
                      Ab + (wm * 64 + mi * 16) * PRS + j * 32 + a_off);
#pragma unroll
            for (int n2 = 0; n2 < 2; n2++) {
                uint32_t b00, b01, b10, b11;
                ldsm4(b00, b01, b10, b11,
                      Bb + (wn * 32 + n2 * 16) * PRS + j * 32 + b_off);
#pragma unroll
                for (int mi = 0; mi < 4; mi++) {
                    mma16(acc[mi][2 * n2],     a[mi], b00, b01);
                    mma16(acc[mi][2 * n2 + 1], a[mi], b10, b11);
                }
            }
        }
        buf = (buf + 1 >= 3) ? 0 : buf + 1;
    }

    // Epilogue: bias + scale, cvt fp16, write head-split [N,H,L,D]
#pragma unroll
    for (int mi = 0; mi < 4; mi++) {
        const int m = m0 + wm * 64 + mi * 16 + g;
#pragma unroll
        for (int ni = 0; ni < 4; ni++) {
            const int c = n0 + wn * 32 + ni * 8 + 2 * t;
            const float b0v = bias[c], b1v = bias[c + 1];
            const int h = c >> 6, d = c & 63;
#pragma unroll
            for (int rh = 0; rh < 2; rh++) {
                const int mm = m + rh * 8;
                const int nbv = mm >> 11, l = mm & 2047;
                const uint32_t val = h2bits(
                    (acc[mi][ni][rh * 2 + 0] + b0v) * scale,
                    (acc[mi][ni][rh * 2 + 1] + b1v) * scale);
                *(uint32_t*)&out[(((size_t)(nbv * HEADS + h)) * L_SEQ + l) * DH + d] = val;
            }
        }
    }
}

// ---------------------------------------------------------------------------
// Flash attention, fp16 m16n8k16 + ldmatrix. 256 thr / 8 warps, warp = 16q.
// Q pre-scaled by log2e -> softmax exp via raw ex2. Row sums l via a ones-
// column mma (constant B frag) -> no per-tile FADD chain, no final shuffles.
// ---------------------------------------------------------------------------
#define SWD 36                                  // word stride (144 B)
#define KBUF 2304                               // 64 * SWD words
#define ATTN_SMEM_WORDS (4 * KBUF)
#define ONE2 0x3C003C00u                        // half2(1.0, 1.0)

__global__ __launch_bounds__(256, 2)
void attn_kernel(const __half* __restrict__ Qg, const __half* __restrict__ Kg,
                 const __half* __restrict__ Vg, const float* __restrict__ mask,
                 float* __restrict__ out)
{
    extern __shared__ uint32_t smw[];
    const uint32_t sa = (uint32_t)__cvta_generic_to_shared(smw);

    const int tid  = threadIdx.x;
    const int lane = tid & 31;
    const int warp = tid >> 5;          // 0..7
    const int g = lane >> 2, t = lane & 3;
    const int nh = blockIdx.y;
    const int nb = nh >> 4, h = nh & 15;
    const int qt = blockIdx.x;
    const int qb = warp * 16;

    const __half* Qb = Qg + ((size_t)nh * L_SEQ + qt * 128) * DH;
    const __half* Kb = Kg + (size_t)nh * L_SEQ * DH;
    const uint16_t* Vb = (const uint16_t*)(Vg + (size_t)nh * L_SEQ * DH);
    const float* mb = mask + nb * L_SEQ;    // pre-scaled by log2e

    const int b_off = ((lane & 7) | ((lane >> 4) << 3)) * 144
                    + ((lane >> 3) & 1) * 16;

    // ---- Stage Q through K region, extract A-frags ----
    {
        const int r = tid >> 1, half = tid & 1;
        const uint4* src = (const uint4*)(Qb + (size_t)r * DH + half * 32);
        uint4* dst = (uint4*)(smw + r * SWD + half * 16);
#pragma unroll
        for (int w = 0; w < 4; w++) dst[w] = src[w];
    }
    __syncthreads();
    uint32_t a_q[4][4];
#pragma unroll
    for (int j = 0; j < 4; j++) {
        const int base = (qb + g) * SWD + 8 * j + t;
        a_q[j][0] = smw[base];
        a_q[j][1] = smw[base + 8 * SWD];
        a_q[j][2] = smw[base + 4];
        a_q[j][3] = smw[base + 8 * SWD + 4];
    }
    __syncthreads();

    const int r  = tid >> 2, ch = tid & 3;     // K staging
    const int kp = tid >> 3, qd = tid & 7;     // V staging

    // ---- Stage K0 / V0 ----
    {
        const uint4* src = (const uint4*)(Kb + (size_t)r * DH + ch * 16);
        uint4* dst = (uint4*)(smw + r * SWD + ch * 8);
        dst[0] = src[0];
        dst[1] = src[1];
#pragma unroll
        for (int i = 0; i < 4; i++) {
            const int d0 = 2 * qd + 16 * i;
            uint32_t a = *(const uint32_t*)(Vb + (size_t)(2 * kp) * DH + d0);
            uint32_t b = *(const uint32_t*)(Vb + (size_t)(2 * kp + 1) * DH + d0);
            smw[2 * KBUF + d0 * SWD + kp]       = prmt(a, b, 0x5410);
            smw[2 * KBUF + (d0 + 1) * SWD + kp] = prmt(a, b, 0x7632);
        }
    }
    __syncthreads();

    float O[8][4];
    float Ol[4] = {0.0f, 0.0f, 0.0f, 0.0f};    // row-sum accumulator (ones col)
#pragma unroll
    for (int nf = 0; nf < 8; nf++)
#pragma unroll
        for (int e = 0; e < 4; e++) O[nf][e] = 0.0f;

    for (int kt = 0; kt < 32; kt++) {
        const int k0 = kt * 64;
        const int cur = kt & 1;
        const bool more = (kt < 31);
        const uint32_t Kc = sa + cur * (KBUF * 4);
        const uint32_t Vc = sa + (2 + cur) * (KBUF * 4);

        uint4 kpre0, kpre1;
        if (more) {
            const uint4* src = (const uint4*)(Kb + (size_t)(k0 + 64 + r) * DH + ch * 16);
            kpre0 = src[0];
            kpre1 = src[1];
        }

        float s[8][4];
#pragma unroll
        for (int nf = 0; nf < 8; nf++)
#pragma unroll
            for (int e = 0; e < 4; e++) s[nf][e] = 0.0f;

#pragma unroll
        for (int j = 0; j < 4; j++) {
#pragma unroll
            for (int u = 0; u < 4; u++) {
                uint32_t b00, b01, b10, b11;
                ldsm4(b00, b01, b10, b11, Kc + u * (16 * 144) + j * 32 + b_off);
                mma16(s[2 * u],     a_q[j], b00, b01);
                mma16(s[2 * u + 1], a_q[j], b10, b11);
            }
        }

        if (more) {
            uint4* dst = (uint4*)(smw + (cur ^ 1) * KBUF + r * SWD + ch * 8);
            dst[0] = kpre0;
            dst[1] = kpre1;
        }

        uint32_t vpa[4], vpb[4];
        if (more) {
#pragma unroll
            for (int i = 0; i < 4; i++) {
                const int d0 = 2 * qd + 16 * i;
                vpa[i] = *(const uint32_t*)(Vb + (size_t)(k0 + 64 + 2 * kp) * DH + d0);
                vpb[i] = *(const uint32_t*)(Vb + (size_t)(k0 + 64 + 2 * kp + 1) * DH + d0);
            }
        }

        // ---- mask(+log2e-folded) + ex2 ----
#pragma unroll
        for (int nf = 0; nf < 8; nf++) {
            const float2 mk = *(const float2*)(mb + k0 + nf * 8 + 2 * t);
            s[nf][0] = ex2f(s[nf][0] + mk.x);
            s[nf][1] = ex2f(s[nf][1] + mk.y);
            s[nf][2] = ex2f(s[nf][2] + mk.x);
            s[nf][3] = ex2f(s[nf][3] + mk.y);
        }

        // ---- O += P V ; l += P * 1 (ones-column mma) ----
#pragma unroll
        for (int j = 0; j < 4; j++) {
            uint32_t pa[4];
            pa[0] = h2bits(s[2*j][0],   s[2*j][1]);
            pa[1] = h2bits(s[2*j][2],   s[2*j][3]);
            pa[2] = h2bits(s[2*j+1][0], s[2*j+1][1]);
            pa[3] = h2bits(s[2*j+1][2], s[2*j+1][3]);
#pragma unroll
            for (int u = 0; u < 4; u++) {
                uint32_t b00, b01, b10, b11;
                ldsm4(b00, b01, b10, b11, Vc + u * (16 * 144) + j * 32 + b_off);
                mma16(O[2 * u],     pa, b00, b01);
                mma16(O[2 * u + 1], pa, b10, b11);
            }
            mma16(Ol, pa, ONE2, ONE2);
        }

        if (more) {
            uint32_t* Vn = smw + (2 + (cur ^ 1)) * KBUF;
#pragma unroll
            for (int i = 0; i < 4; i++) {
                const int d0 = 2 * qd + 16 * i;
                Vn[d0 * SWD + kp]       = prmt(vpa[i], vpb[i], 0x5410);
                Vn[(d0 + 1) * SWD + kp] = prmt(vpa[i], vpb[i], 0x7632);
            }
        }
        __syncthreads();
    }

    // ---- epilogue: normalize by l (Ol[0]=row g, Ol[2]=row g+8) ----
    {
        const int r0 = qt * 128 + qb + g;
        const float inv0 = 1.0f / Ol[0];
        const float inv1 = 1.0f / Ol[2];
#pragma unroll
        for (int nf = 0; nf < 8; nf++) {
            const int d = h * DH + nf * 8 + 2 * t;
            float* o0 = out + ((size_t)(nb * L_SEQ + r0)) * EMB + d;
            float* o1 = out + ((size_t)(nb * L_SEQ + r0 + 8)) * EMB + d;
            *(float2*)o0 = make_float2(O[nf][0] * inv0, O[nf][1] * inv0);
            *(float2*)o1 = make_float2(O[nf][2] * inv1, O[nf][3] * inv1);
        }
    }
}

// ---------------------------------------------------------------------------
// Launch
// ---------------------------------------------------------------------------
extern "C" void kernel_launch(void* const* d_in, const int* in_sizes, int n_in,
                              void* d_out, int out_size)
{
    const float* x    = (const float*)d_in[0];
    const float* mask = (const float*)d_in[1];
    const float* Wq   = (const float*)d_in[2];
    const float* bq   = (const float*)d_in[3];
    const float* Wk   = (const float*)d_in[4];
    const float* bk   = (const float*)d_in[5];
    const float* Wv   = (const float*)d_in[6];
    const float* bv   = (const float*)d_in[7];
    float* out = (float*)d_out;

    __half *gq, *gk, *gv, *gx, *gw;
    float* gm;
    cudaGetSymbolAddress((void**)&gq, g_Q);
    cudaGetSymbolAddress((void**)&gk, g_K);
    cudaGetSymbolAddress((void**)&gv, g_V);
    cudaGetSymbolAddress((void**)&gx, g_X);
    cudaGetSymbolAddress((void**)&gw, g_W);
    cudaGetSymbolAddress((void**)&gm, g_M);

    const int proj_smem = PROJ_SMEM;             // 110592 B
    const int attn_smem = ATTN_SMEM_WORDS * 4;   // 36864 B

    static int smem_set = 0;
    if (!smem_set) {
        cudaFuncSetAttribute(proj_kernel,
                             cudaFuncAttributeMaxDynamicSharedMemorySize,
                             proj_smem);
        cudaFuncSetAttribute(attn_kernel,
                             cudaFuncAttributeMaxDynamicSharedMemorySize,
                             attn_smem);
        smem_set = 1;
    }

    cvt_all_kernel<<<XB + 3 * WB + MB, 256>>>(
        (const float4*)x, (const float4*)Wq, (const float4*)Wk,
        (const float4*)Wv, (const float4*)mask,
        (uint2*)gx, (uint2*)gw, (float4*)gm);

    dim3 pg(EMB / 128, MROWS / 128, 3);   // (8, 64, 3)
    proj_kernel<<<pg, 256, proj_smem>>>(gx, gw, bq, bk, bv, gq, gk, gv);

    dim3 ag(L_SEQ / 128, NBATCH * HEADS); // (16, 64)
    attn_kernel<<<ag, 256, attn_smem>>>(gq, gk, gv, gm, out);
}